// round 1
// baseline (speedup 1.0000x reference)
#include <cuda_runtime.h>
#include <math.h>

// ---------------------------------------------------------------------------
// Problem constants
// ---------------------------------------------------------------------------
#define NB   32
#define PP   1024
#define C0   64
#define KNN  16
#define NPTS (NB * PP)       // 32768
#define ROWS (NPTS * KNN)    // 524288
#define LRELU_ALPHA 0.1f
#define BN_EPS 1e-3f

// ---------------------------------------------------------------------------
// Static device scratch (no allocations allowed)
// ---------------------------------------------------------------------------
__device__ float d_A  [NPTS * 128];      // features @ (W0[:64]-W0[64:])
__device__ float d_B  [NPTS * 128];      // features @ W0[64:]
__device__ float d_SC [NPTS * 256];      // features @ Wsc (pre-BN)
__device__ float d_buf1[ROWS * 128];     // y0 / x1
__device__ float d_buf2[ROWS * 128];     // y1 / x2
__device__ float d_buf3[ROWS * 256];     // y2 (pre-BN)
__device__ int   d_idx [ROWS];           // knn indices, flat (np*16+k)
__device__ float d_WA  [64 * 128];       // W0[:64]-W0[64:]
__device__ float d_sum  [4 * 256];
__device__ float d_sumsq[4 * 256];
__device__ float d_scale[4 * 256];
__device__ float d_shift[4 * 256];

// ---------------------------------------------------------------------------
// Zero the stats accumulators
// ---------------------------------------------------------------------------
__global__ void zero_stats_kernel() {
    int t = blockIdx.x * blockDim.x + threadIdx.x;
    if (t < 4 * 256) { d_sum[t] = 0.f; d_sumsq[t] = 0.f; }
}

// ---------------------------------------------------------------------------
// WA = W0[:64,:] - W0[64:,:]
// ---------------------------------------------------------------------------
__global__ void prep_wa_kernel(const float* __restrict__ W0) {
    int t = blockIdx.x * blockDim.x + threadIdx.x;
    if (t < 64 * 128) d_WA[t] = W0[t] - W0[64 * 128 + t];
}

// ---------------------------------------------------------------------------
// KNN: for each point, 16 nearest (excluding self). Order irrelevant
// (consumed only through a mean over k).
// grid: 128 blocks (4 per batch), 256 threads, one query per thread.
// ---------------------------------------------------------------------------
__global__ void knn_kernel(const float* __restrict__ pts) {
    __shared__ float sx[PP], sy[PP], sz[PP];
    int n = blockIdx.x >> 2;
    int p = ((blockIdx.x & 3) << 8) + threadIdx.x;
    const float* base = pts + (size_t)n * PP * 3;
    for (int i = threadIdx.x; i < PP; i += blockDim.x) {
        sx[i] = base[i * 3 + 0];
        sy[i] = base[i * 3 + 1];
        sz[i] = base[i * 3 + 2];
    }
    __syncthreads();

    float qx = sx[p], qy = sy[p], qz = sz[p];
    float bd[KNN];
    int   bi[KNN];
#pragma unroll
    for (int i = 0; i < KNN; i++) { bd[i] = 3.0e38f; bi[i] = 0; }

    for (int q = 0; q < PP; q++) {
        float dx = sx[q] - qx, dy = sy[q] - qy, dz = sz[q] - qz;
        float d = dx * dx + dy * dy + dz * dz;
        if (q == p) continue;
        if (d < bd[KNN - 1]) {
            int j = KNN - 1;
            while (j > 0 && bd[j - 1] > d) {
                bd[j] = bd[j - 1]; bi[j] = bi[j - 1]; j--;
            }
            bd[j] = d; bi[j] = q;
        }
    }
    int ob = (n * PP + p) * KNN;
    for (int k = 0; k < KNN; k++) d_idx[ob + k] = bi[k];
}

// ---------------------------------------------------------------------------
// Generic fp32 tiled GEMM: Y[M,N] = X[M,Kc] @ W[Kc,N]
// BM=128, BN=128, BK=8, 256 threads, 8x8 per-thread tile.
// Optional fused per-channel sum / sumsq accumulation (for BN stats).
// M%128==0, N%128==0, Kc%8==0 guaranteed by caller.
// ---------------------------------------------------------------------------
#define GBM 128
#define GBN 128
#define GBK 8

template <bool STATS>
__global__ void gemm_kernel(const float* __restrict__ X,
                            const float* __restrict__ W,
                            float* __restrict__ Y,
                            int M, int Kc, int N,
                            float* sumArr, float* sumsqArr) {
    __shared__ float As[GBK][GBM];
    __shared__ float Bs[GBK][GBN];

    int tid = threadIdx.x;
    int rowBase = blockIdx.x * GBM;
    int colBase = blockIdx.y * GBN;
    int tx = tid & 15;       // N direction
    int ty = tid >> 4;       // M direction

    float acc[8][8];
#pragma unroll
    for (int i = 0; i < 8; i++)
#pragma unroll
        for (int j = 0; j < 8; j++) acc[i][j] = 0.f;

    int a_row = tid >> 1;            // 0..127
    int a_k4  = (tid & 1) * 4;       // 0 or 4
    int b_k   = tid >> 5;            // 0..7
    int b_n   = (tid & 31) * 4;      // 0..124

    for (int k0 = 0; k0 < Kc; k0 += GBK) {
        float4 av = *(const float4*)&X[(size_t)(rowBase + a_row) * Kc + k0 + a_k4];
        As[a_k4 + 0][a_row] = av.x;
        As[a_k4 + 1][a_row] = av.y;
        As[a_k4 + 2][a_row] = av.z;
        As[a_k4 + 3][a_row] = av.w;
        float4 bv = *(const float4*)&W[(size_t)(k0 + b_k) * N + colBase + b_n];
        *(float4*)&Bs[b_k][b_n] = bv;
        __syncthreads();

#pragma unroll
        for (int kk = 0; kk < GBK; kk++) {
            float4 a0 = *(const float4*)&As[kk][ty * 8];
            float4 a1 = *(const float4*)&As[kk][ty * 8 + 4];
            float4 b0 = *(const float4*)&Bs[kk][tx * 8];
            float4 b1 = *(const float4*)&Bs[kk][tx * 8 + 4];
            float a[8] = {a0.x, a0.y, a0.z, a0.w, a1.x, a1.y, a1.z, a1.w};
            float b[8] = {b0.x, b0.y, b0.z, b0.w, b1.x, b1.y, b1.z, b1.w};
#pragma unroll
            for (int i = 0; i < 8; i++)
#pragma unroll
                for (int j = 0; j < 8; j++) acc[i][j] += a[i] * b[j];
        }
        __syncthreads();
    }

#pragma unroll
    for (int i = 0; i < 8; i++) {
        int row = rowBase + ty * 8 + i;
        float4 c0 = {acc[i][0], acc[i][1], acc[i][2], acc[i][3]};
        float4 c1 = {acc[i][4], acc[i][5], acc[i][6], acc[i][7]};
        *(float4*)&Y[(size_t)row * N + colBase + tx * 8]     = c0;
        *(float4*)&Y[(size_t)row * N + colBase + tx * 8 + 4] = c1;
    }

    if constexpr (STATS) {
        __shared__ float ssum[GBN];
        __shared__ float ssq[GBN];
        if (tid < GBN) { ssum[tid] = 0.f; ssq[tid] = 0.f; }
        __syncthreads();
#pragma unroll
        for (int j = 0; j < 8; j++) {
            float s = 0.f, q = 0.f;
#pragma unroll
            for (int i = 0; i < 8; i++) {
                s += acc[i][j];
                q += acc[i][j] * acc[i][j];
            }
            atomicAdd(&ssum[tx * 8 + j], s);
            atomicAdd(&ssq [tx * 8 + j], q);
        }
        __syncthreads();
        if (tid < GBN) {
            atomicAdd(&sumArr  [colBase + tid], ssum[tid]);
            atomicAdd(&sumsqArr[colBase + tid], ssq[tid]);
        }
    }
}

// ---------------------------------------------------------------------------
// Layer0 via gather: y0[np,k,:] = A[np,:] + B[n, idx[np,k], :]  (+ stats)
// buf1 as float4 (128 ch = 32 float4/row). grid: 2048x256, stride % 32 == 0
// so each thread's channel-quad is fixed -> register partial stats.
// ---------------------------------------------------------------------------
__global__ void gather_stats_kernel() {
    const float4* A4 = (const float4*)d_A;
    const float4* B4 = (const float4*)d_B;
    float4* Y4 = (float4*)d_buf1;
    __shared__ float ssum[128], ssq[128];
    if (threadIdx.x < 128) { ssum[threadIdx.x] = 0.f; ssq[threadIdx.x] = 0.f; }
    __syncthreads();

    int start  = blockIdx.x * blockDim.x + threadIdx.x;
    int stride = gridDim.x * blockDim.x;          // 524288, % 32 == 0
    int c4 = start & 31;
    const int total = ROWS * 32;

    float s0 = 0, s1 = 0, s2 = 0, s3 = 0;
    float q0 = 0, q1 = 0, q2 = 0, q3 = 0;
    for (int e = start; e < total; e += stride) {
        int r  = e >> 5;
        int cc = e & 31;
        int np = r >> 4;
        int n  = np >> 10;
        int id = d_idx[r];
        float4 a = A4[np * 32 + cc];
        float4 b = B4[(n * 1024 + id) * 32 + cc];
        float4 y;
        y.x = a.x + b.x; y.y = a.y + b.y; y.z = a.z + b.z; y.w = a.w + b.w;
        Y4[e] = y;
        s0 += y.x; q0 += y.x * y.x;
        s1 += y.y; q1 += y.y * y.y;
        s2 += y.z; q2 += y.z * y.z;
        s3 += y.w; q3 += y.w * y.w;
    }
    atomicAdd(&ssum[c4 * 4 + 0], s0); atomicAdd(&ssq[c4 * 4 + 0], q0);
    atomicAdd(&ssum[c4 * 4 + 1], s1); atomicAdd(&ssq[c4 * 4 + 1], q1);
    atomicAdd(&ssum[c4 * 4 + 2], s2); atomicAdd(&ssq[c4 * 4 + 2], q2);
    atomicAdd(&ssum[c4 * 4 + 3], s3); atomicAdd(&ssq[c4 * 4 + 3], q3);
    __syncthreads();
    if (threadIdx.x < 128) {
        atomicAdd(&d_sum  [threadIdx.x], ssum[threadIdx.x]);
        atomicAdd(&d_sumsq[threadIdx.x], ssq[threadIdx.x]);
    }
}

// ---------------------------------------------------------------------------
// Stats -> (scale, shift):  scale = g * rsqrt(var+eps); shift = b - mean*scale
// ---------------------------------------------------------------------------
__global__ void finalize_kernel(int layer, const float* __restrict__ g,
                                const float* __restrict__ b, float cnt, int nch) {
    int c = threadIdx.x;
    if (c < nch) {
        float mean = d_sum[layer * 256 + c] / cnt;
        float var  = d_sumsq[layer * 256 + c] / cnt - mean * mean;
        float sc = g[c] * rsqrtf(var + BN_EPS);
        d_scale[layer * 256 + c] = sc;
        d_shift[layer * 256 + c] = b[c] - mean * sc;
    }
}

// ---------------------------------------------------------------------------
// In-place BN + LeakyReLU on a [rows, C] buffer (C = 4*(cmask+1))
// ---------------------------------------------------------------------------
__global__ void norm_lrelu_kernel(float* __restrict__ Y, int total4, int cmask,
                                  int layer) {
    const float* sc = d_scale + layer * 256;
    const float* sh = d_shift + layer * 256;
    int start  = blockIdx.x * blockDim.x + threadIdx.x;
    int stride = gridDim.x * blockDim.x;
    float4* Y4 = (float4*)Y;
    for (int e = start; e < total4; e += stride) {
        int c = (e & cmask) * 4;
        float4 v = Y4[e];
        float x0 = v.x * sc[c + 0] + sh[c + 0];
        float x1 = v.y * sc[c + 1] + sh[c + 1];
        float x2 = v.z * sc[c + 2] + sh[c + 2];
        float x3 = v.w * sc[c + 3] + sh[c + 3];
        v.x = x0 > 0.f ? x0 : LRELU_ALPHA * x0;
        v.y = x1 > 0.f ? x1 : LRELU_ALPHA * x1;
        v.z = x2 > 0.f ? x2 : LRELU_ALPHA * x2;
        v.w = x3 > 0.f ? x3 : LRELU_ALPHA * x3;
        Y4[e] = v;
    }
}

// ---------------------------------------------------------------------------
// Epilogue: out = lrelu( BN_sc(SC) + mean_k lrelu(BN2(y2)) )
// One thread per (np, channel-quad). 256 channels -> 64 float4 per row.
// ---------------------------------------------------------------------------
__global__ void final_kernel(float* __restrict__ out) {
    int t = blockIdx.x * blockDim.x + threadIdx.x;
    if (t >= NPTS * 64) return;
    int np = t >> 6;
    int c4 = t & 63;

    float4 s2 = *(const float4*)&d_scale[2 * 256 + c4 * 4];
    float4 h2 = *(const float4*)&d_shift[2 * 256 + c4 * 4];
    float4 s3 = *(const float4*)&d_scale[3 * 256 + c4 * 4];
    float4 h3 = *(const float4*)&d_shift[3 * 256 + c4 * 4];

    const float4* Y4 = (const float4*)d_buf3;
    int base = np * 16 * 64 + c4;
    float ax = 0, ay = 0, az = 0, aw = 0;
#pragma unroll
    for (int k = 0; k < KNN; k++) {
        float4 v = Y4[base + k * 64];
        float x0 = v.x * s2.x + h2.x;
        float x1 = v.y * s2.y + h2.y;
        float x2 = v.z * s2.z + h2.z;
        float x3 = v.w * s2.w + h2.w;
        ax += x0 > 0.f ? x0 : LRELU_ALPHA * x0;
        ay += x1 > 0.f ? x1 : LRELU_ALPHA * x1;
        az += x2 > 0.f ? x2 : LRELU_ALPHA * x2;
        aw += x3 > 0.f ? x3 : LRELU_ALPHA * x3;
    }
    const float inv = 1.0f / (float)KNN;
    float4 s = ((const float4*)d_SC)[np * 64 + c4];
    float r0 = s.x * s3.x + h3.x + ax * inv;
    float r1 = s.y * s3.y + h3.y + ay * inv;
    float r2 = s.z * s3.z + h3.z + az * inv;
    float r3 = s.w * s3.w + h3.w + aw * inv;
    float4 o;
    o.x = r0 > 0.f ? r0 : LRELU_ALPHA * r0;
    o.y = r1 > 0.f ? r1 : LRELU_ALPHA * r1;
    o.z = r2 > 0.f ? r2 : LRELU_ALPHA * r2;
    o.w = r3 > 0.f ? r3 : LRELU_ALPHA * r3;
    ((float4*)out)[t] = o;
}

// ---------------------------------------------------------------------------
// Launch
// ---------------------------------------------------------------------------
extern "C" void kernel_launch(void* const* d_in, const int* in_sizes, int n_in,
                              void* d_out, int out_size) {
    const float* points   = (const float*)d_in[0];
    const float* features = (const float*)d_in[1];
    const float* W0  = (const float*)d_in[2];
    const float* g0  = (const float*)d_in[3];
    const float* b0  = (const float*)d_in[4];
    const float* W1  = (const float*)d_in[5];
    const float* g1  = (const float*)d_in[6];
    const float* b1  = (const float*)d_in[7];
    const float* W2  = (const float*)d_in[8];
    const float* g2  = (const float*)d_in[9];
    const float* b2  = (const float*)d_in[10];
    const float* Wsc = (const float*)d_in[11];
    const float* gsc = (const float*)d_in[12];
    const float* bsc = (const float*)d_in[13];
    float* out = (float*)d_out;

    float *pA, *pB, *pSC, *p1, *p2, *p3, *pWA, *psum, *psq;
    cudaGetSymbolAddress((void**)&pA,  d_A);
    cudaGetSymbolAddress((void**)&pB,  d_B);
    cudaGetSymbolAddress((void**)&pSC, d_SC);
    cudaGetSymbolAddress((void**)&p1,  d_buf1);
    cudaGetSymbolAddress((void**)&p2,  d_buf2);
    cudaGetSymbolAddress((void**)&p3,  d_buf3);
    cudaGetSymbolAddress((void**)&pWA, d_WA);
    cudaGetSymbolAddress((void**)&psum, d_sum);
    cudaGetSymbolAddress((void**)&psq,  d_sumsq);

    zero_stats_kernel<<<4, 256>>>();
    knn_kernel<<<128, 256>>>(points);
    prep_wa_kernel<<<32, 256>>>(W0);

    // A = f @ WA ; B = f @ W0[64:] ; SC = f @ Wsc (with stats, layer 3)
    gemm_kernel<false><<<dim3(NPTS / GBM, 1), 256>>>(features, pWA, pA,
                                                     NPTS, 64, 128, nullptr, nullptr);
    gemm_kernel<false><<<dim3(NPTS / GBM, 1), 256>>>(features, W0 + 64 * 128, pB,
                                                     NPTS, 64, 128, nullptr, nullptr);
    gemm_kernel<true><<<dim3(NPTS / GBM, 2), 256>>>(features, Wsc, pSC,
                                                    NPTS, 64, 256,
                                                    psum + 3 * 256, psq + 3 * 256);
    finalize_kernel<<<1, 256>>>(3, gsc, bsc, (float)NPTS, 256);

    // layer 0: gather + stats, finalize, normalize
    gather_stats_kernel<<<2048, 256>>>();
    finalize_kernel<<<1, 256>>>(0, g0, b0, (float)ROWS, 128);
    norm_lrelu_kernel<<<2048, 256>>>(p1, ROWS * 32, 31, 0);

    // layer 1
    gemm_kernel<true><<<dim3(ROWS / GBM, 1), 256>>>(p1, W1, p2, ROWS, 128, 128,
                                                    psum + 1 * 256, psq + 1 * 256);
    finalize_kernel<<<1, 256>>>(1, g1, b1, (float)ROWS, 128);
    norm_lrelu_kernel<<<2048, 256>>>(p2, ROWS * 32, 31, 1);

    // layer 2 (stats only; BN+lrelu fused into epilogue)
    gemm_kernel<true><<<dim3(ROWS / GBM, 2), 256>>>(p2, W2, p3, ROWS, 128, 256,
                                                    psum + 2 * 256, psq + 2 * 256);
    finalize_kernel<<<1, 256>>>(2, g2, b2, (float)ROWS, 256);

    final_kernel<<<NPTS * 64 / 256, 256>>>(out);
}

// round 3
// speedup vs baseline: 1.0634x; 1.0634x over previous
#include <cuda_runtime.h>
#include <math.h>
#include <cstdint>

// ---------------------------------------------------------------------------
// Problem constants
// ---------------------------------------------------------------------------
#define NB   32
#define PP   1024
#define C0   64
#define KNN  16
#define NPTS (NB * PP)       // 32768
#define ROWS (NPTS * KNN)    // 524288
#define LRELU_ALPHA 0.1f
#define BN_EPS 1e-3f

// ---------------------------------------------------------------------------
// Static device scratch
// ---------------------------------------------------------------------------
__device__ float d_A  [NPTS * 128];      // features @ (W0[:64]-W0[64:])
__device__ float d_B  [NPTS * 128];      // features @ W0[64:]
__device__ float d_SC [NPTS * 256];      // features @ Wsc (pre-BN)
__device__ float d_buf2[ROWS * 128];     // y1 (pre-BN)
__device__ float d_buf3[ROWS * 256];     // y2 (pre-BN)
__device__ int   d_idx [ROWS];
__device__ float d_WA  [64 * 128];
__device__ float d_sum  [4 * 256];
__device__ float d_sumsq[4 * 256];
__device__ float d_scale[4 * 256];
__device__ float d_shift[4 * 256];

__device__ __forceinline__ uint32_t f2tf32(float x) {
    uint32_t u; asm("cvt.rna.tf32.f32 %0, %1;" : "=r"(u) : "f"(x)); return u;
}
__device__ __forceinline__ void mma_tf32(float* d, const uint32_t* a, const uint32_t* b) {
    asm volatile(
        "mma.sync.aligned.m16n8k8.row.col.f32.tf32.tf32.f32 "
        "{%0,%1,%2,%3}, {%4,%5,%6,%7}, {%8,%9}, {%0,%1,%2,%3};"
        : "+f"(d[0]), "+f"(d[1]), "+f"(d[2]), "+f"(d[3])
        : "r"(a[0]), "r"(a[1]), "r"(a[2]), "r"(a[3]), "r"(b[0]), "r"(b[1]));
}

__global__ void zero_stats_kernel() {
    int t = blockIdx.x * blockDim.x + threadIdx.x;
    if (t < 4 * 256) { d_sum[t] = 0.f; d_sumsq[t] = 0.f; }
}
__global__ void prep_wa_kernel(const float* __restrict__ W0) {
    int t = blockIdx.x * blockDim.x + threadIdx.x;
    if (t < 64 * 128) d_WA[t] = W0[t] - W0[64 * 128 + t];
}

// ---------------------------------------------------------------------------
// KNN: 16 nearest excluding self (order irrelevant; consumed via mean over k)
// ---------------------------------------------------------------------------
__global__ void knn_kernel(const float* __restrict__ pts) {
    __shared__ float sx[PP], sy[PP], sz[PP];
    int n = blockIdx.x >> 2;
    int p = ((blockIdx.x & 3) << 8) + threadIdx.x;
    const float* base = pts + (size_t)n * PP * 3;
    for (int i = threadIdx.x; i < PP; i += blockDim.x) {
        sx[i] = base[i * 3 + 0];
        sy[i] = base[i * 3 + 1];
        sz[i] = base[i * 3 + 2];
    }
    __syncthreads();
    float qx = sx[p], qy = sy[p], qz = sz[p];
    float bd[KNN]; int bi[KNN];
#pragma unroll
    for (int i = 0; i < KNN; i++) { bd[i] = 3.0e38f; bi[i] = 0; }
    for (int q = 0; q < PP; q++) {
        float dx = sx[q] - qx, dy = sy[q] - qy, dz = sz[q] - qz;
        float d = dx * dx + dy * dy + dz * dz;
        if (q == p) continue;
        if (d < bd[KNN - 1]) {
            int j = KNN - 1;
            while (j > 0 && bd[j - 1] > d) { bd[j] = bd[j - 1]; bi[j] = bi[j - 1]; j--; }
            bd[j] = d; bi[j] = q;
        }
    }
    int ob = (n * PP + p) * KNN;
    for (int k = 0; k < KNN; k++) d_idx[ob + k] = bi[k];
}

// ---------------------------------------------------------------------------
// SIMT fp32 GEMM for the small feature matmuls (M=32768, K=64) — kept fp32
// ---------------------------------------------------------------------------
#define GBM 128
#define GBN 128
#define GBK 8
template <bool STATS>
__global__ void gemm_kernel(const float* __restrict__ X, const float* __restrict__ W,
                            float* __restrict__ Y, int M, int Kc, int N,
                            float* sumArr, float* sumsqArr) {
    __shared__ float As[GBK][GBM];
    __shared__ float Bs[GBK][GBN];
    int tid = threadIdx.x;
    int rowBase = blockIdx.x * GBM;
    int colBase = blockIdx.y * GBN;
    int tx = tid & 15, ty = tid >> 4;
    float acc[8][8];
#pragma unroll
    for (int i = 0; i < 8; i++)
#pragma unroll
        for (int j = 0; j < 8; j++) acc[i][j] = 0.f;
    int a_row = tid >> 1, a_k4 = (tid & 1) * 4;
    int b_k = tid >> 5, b_n = (tid & 31) * 4;
    for (int k0 = 0; k0 < Kc; k0 += GBK) {
        float4 av = *(const float4*)&X[(size_t)(rowBase + a_row) * Kc + k0 + a_k4];
        As[a_k4 + 0][a_row] = av.x; As[a_k4 + 1][a_row] = av.y;
        As[a_k4 + 2][a_row] = av.z; As[a_k4 + 3][a_row] = av.w;
        float4 bv = *(const float4*)&W[(size_t)(k0 + b_k) * N + colBase + b_n];
        *(float4*)&Bs[b_k][b_n] = bv;
        __syncthreads();
#pragma unroll
        for (int kk = 0; kk < GBK; kk++) {
            float4 a0 = *(const float4*)&As[kk][ty * 8];
            float4 a1 = *(const float4*)&As[kk][ty * 8 + 4];
            float4 b0 = *(const float4*)&Bs[kk][tx * 8];
            float4 b1 = *(const float4*)&Bs[kk][tx * 8 + 4];
            float a[8] = {a0.x, a0.y, a0.z, a0.w, a1.x, a1.y, a1.z, a1.w};
            float b[8] = {b0.x, b0.y, b0.z, b0.w, b1.x, b1.y, b1.z, b1.w};
#pragma unroll
            for (int i = 0; i < 8; i++)
#pragma unroll
                for (int j = 0; j < 8; j++) acc[i][j] += a[i] * b[j];
        }
        __syncthreads();
    }
#pragma unroll
    for (int i = 0; i < 8; i++) {
        int row = rowBase + ty * 8 + i;
        float4 c0 = {acc[i][0], acc[i][1], acc[i][2], acc[i][3]};
        float4 c1 = {acc[i][4], acc[i][5], acc[i][6], acc[i][7]};
        *(float4*)&Y[(size_t)row * N + colBase + tx * 8]     = c0;
        *(float4*)&Y[(size_t)row * N + colBase + tx * 8 + 4] = c1;
    }
    if constexpr (STATS) {
        __shared__ float ssum[GBN], ssq[GBN];
        if (tid < GBN) { ssum[tid] = 0.f; ssq[tid] = 0.f; }
        __syncthreads();
#pragma unroll
        for (int j = 0; j < 8; j++) {
            float s = 0.f, q = 0.f;
#pragma unroll
            for (int i = 0; i < 8; i++) { s += acc[i][j]; q += acc[i][j] * acc[i][j]; }
            atomicAdd(&ssum[tx * 8 + j], s);
            atomicAdd(&ssq [tx * 8 + j], q);
        }
        __syncthreads();
        if (tid < GBN) {
            atomicAdd(&sumArr  [colBase + tid], ssum[tid]);
            atomicAdd(&sumsqArr[colBase + tid], ssq[tid]);
        }
    }
}

// ---------------------------------------------------------------------------
// Layer-0 BN stats without materializing y0: y0 = A[np] + B[idx]
// ---------------------------------------------------------------------------
__global__ void l0_stats_kernel() {
    const float4* A4 = (const float4*)d_A;
    const float4* B4 = (const float4*)d_B;
    __shared__ float ssum[128], ssq[128];
    if (threadIdx.x < 128) { ssum[threadIdx.x] = 0.f; ssq[threadIdx.x] = 0.f; }
    __syncthreads();
    int start  = blockIdx.x * blockDim.x + threadIdx.x;
    int stride = gridDim.x * blockDim.x;
    int c4 = start & 31;
    const int total = ROWS * 32;
    float s0 = 0, s1 = 0, s2 = 0, s3 = 0;
    float q0 = 0, q1 = 0, q2 = 0, q3 = 0;
    for (int e = start; e < total; e += stride) {
        int r = e >> 5, cc = e & 31;
        int np = r >> 4, n = np >> 10;
        int id = d_idx[r];
        float4 a = A4[np * 32 + cc];
        float4 b = B4[(n * 1024 + id) * 32 + cc];
        float yx = a.x + b.x, yy = a.y + b.y, yz = a.z + b.z, yw = a.w + b.w;
        s0 += yx; q0 += yx * yx; s1 += yy; q1 += yy * yy;
        s2 += yz; q2 += yz * yz; s3 += yw; q3 += yw * yw;
    }
    atomicAdd(&ssum[c4 * 4 + 0], s0); atomicAdd(&ssq[c4 * 4 + 0], q0);
    atomicAdd(&ssum[c4 * 4 + 1], s1); atomicAdd(&ssq[c4 * 4 + 1], q1);
    atomicAdd(&ssum[c4 * 4 + 2], s2); atomicAdd(&ssq[c4 * 4 + 2], q2);
    atomicAdd(&ssum[c4 * 4 + 3], s3); atomicAdd(&ssq[c4 * 4 + 3], q3);
    __syncthreads();
    if (threadIdx.x < 128) {
        atomicAdd(&d_sum  [threadIdx.x], ssum[threadIdx.x]);
        atomicAdd(&d_sumsq[threadIdx.x], ssq[threadIdx.x]);
    }
}

__global__ void finalize_kernel(int layer, const float* __restrict__ g,
                                const float* __restrict__ b, float cnt, int nch) {
    int c = threadIdx.x;
    if (c < nch) {
        float mean = d_sum[layer * 256 + c] / cnt;
        float var  = d_sumsq[layer * 256 + c] / cnt - mean * mean;
        float sc = g[c] * rsqrtf(var + BN_EPS);
        d_scale[layer * 256 + c] = sc;
        d_shift[layer * 256 + c] = b[c] - mean * sc;
    }
}

// ---------------------------------------------------------------------------
// tf32 mma.sync GEMM: BM=128, BN=128, K=128 in one shot. 256 thr = 8 warps
// (4 row x 2 col), warp tile 32x64, m16n8k8, fully unrolled.
// MODE 0: A-tile = lrelu(BN0(gather A+B))   (layer-1 GEMM)
// MODE 1: A-tile = lrelu(BN1(buf2))         (layer-2 GEMM)
// Epilogue: raw y to Y + per-channel sum/sumsq via xor-shuffle + atomics.
// smem rows padded to 132 words -> fragment LDS pattern is conflict-free.
// ---------------------------------------------------------------------------
#define APAD 132
template <int N_TOT, int MODE>
__global__ void __launch_bounds__(256, 1) gemm_mma_kernel(
    const float* __restrict__ Xin, const float* __restrict__ W,
    float* __restrict__ Y, int layer_in, int layer_out) {
    extern __shared__ char smem_raw[];
    uint32_t* As = (uint32_t*)smem_raw;                       // [128][APAD]
    uint32_t* Bs = As + 128 * APAD;                           // [128][APAD]
    float*  ssum = (float*)(Bs + 128 * APAD);                 // [128]
    float*  ssq  = ssum + 128;

    const int tid = threadIdx.x;
    const int wid = tid >> 5;
    const int lane = tid & 31;
    const int gid = lane >> 2;     // group (row within fragment)
    const int tg  = lane & 3;      // thread in group (col within fragment)
    const int warpRow = wid & 3;   // 4 row-warps * 32 rows
    const int warpCol = wid >> 2;  // 2 col-warps * 64 cols
    const int tileBase = blockIdx.x * 128;
    const int colBase  = blockIdx.y * 128;

    if (tid < 128) { ssum[tid] = 0.f; ssq[tid] = 0.f; }

    // ---- B tile: Bs[n][k] = tf32(W[k][colBase+n]) --------------------------
    for (int e = tid; e < 128 * 128; e += 256) {
        int k = e >> 7, n = e & 127;
        Bs[n * APAD + k] = f2tf32(W[(size_t)k * N_TOT + colBase + n]);
    }

    // ---- A tile (fused elementwise producer) -------------------------------
    const float4* sc4 = (const float4*)&d_scale[layer_in * 256];
    const float4* sh4 = (const float4*)&d_shift[layer_in * 256];
    for (int e = tid; e < 128 * 32; e += 256) {
        int r = e >> 5, cc = e & 31;
        int R = tileBase + r;
        float4 x;
        if (MODE == 0) {
            int np = R >> 4, n = np >> 10;
            int id = d_idx[R];
            float4 a = ((const float4*)d_A)[np * 32 + cc];
            float4 b = ((const float4*)d_B)[(n * 1024 + id) * 32 + cc];
            x.x = a.x + b.x; x.y = a.y + b.y; x.z = a.z + b.z; x.w = a.w + b.w;
        } else {
            x = ((const float4*)Xin)[(size_t)R * 32 + cc];
        }
        float4 sc = sc4[cc], sh = sh4[cc];
        float x0 = x.x * sc.x + sh.x, x1 = x.y * sc.y + sh.y;
        float x2 = x.z * sc.z + sh.z, x3 = x.w * sc.w + sh.w;
        x0 = x0 > 0.f ? x0 : LRELU_ALPHA * x0;
        x1 = x1 > 0.f ? x1 : LRELU_ALPHA * x1;
        x2 = x2 > 0.f ? x2 : LRELU_ALPHA * x2;
        x3 = x3 > 0.f ? x3 : LRELU_ALPHA * x3;
        uint32_t* dst = &As[r * APAD + cc * 4];
        dst[0] = f2tf32(x0); dst[1] = f2tf32(x1);
        dst[2] = f2tf32(x2); dst[3] = f2tf32(x3);
    }
    __syncthreads();

    // ---- MMA main: warp tile 32x64, 16 K-steps -----------------------------
    float c[2][8][4];
#pragma unroll
    for (int mi = 0; mi < 2; mi++)
#pragma unroll
        for (int ni = 0; ni < 8; ni++)
#pragma unroll
            for (int j = 0; j < 4; j++) c[mi][ni][j] = 0.f;

#pragma unroll
    for (int k0 = 0; k0 < 128; k0 += 8) {
        uint32_t af[2][4], bf[8][2];
#pragma unroll
        for (int mi = 0; mi < 2; mi++) {
            int mb = warpRow * 32 + mi * 16;
            af[mi][0] = As[(mb + gid    ) * APAD + k0 + tg];
            af[mi][1] = As[(mb + gid + 8) * APAD + k0 + tg];
            af[mi][2] = As[(mb + gid    ) * APAD + k0 + tg + 4];
            af[mi][3] = As[(mb + gid + 8) * APAD + k0 + tg + 4];
        }
#pragma unroll
        for (int ni = 0; ni < 8; ni++) {
            int nb = warpCol * 64 + ni * 8 + gid;
            bf[ni][0] = Bs[nb * APAD + k0 + tg];
            bf[ni][1] = Bs[nb * APAD + k0 + tg + 4];
        }
#pragma unroll
        for (int mi = 0; mi < 2; mi++)
#pragma unroll
            for (int ni = 0; ni < 8; ni++)
                mma_tf32(c[mi][ni], af[mi], bf[ni]);
    }

    // ---- Epilogue: store raw y, accumulate stats ---------------------------
#pragma unroll
    for (int mi = 0; mi < 2; mi++) {
        size_t r0 = (size_t)tileBase + warpRow * 32 + mi * 16 + gid;
#pragma unroll
        for (int ni = 0; ni < 8; ni++) {
            int col = colBase + warpCol * 64 + ni * 8 + tg * 2;
            float2 v0 = {c[mi][ni][0], c[mi][ni][1]};
            float2 v1 = {c[mi][ni][2], c[mi][ni][3]};
            *(float2*)&Y[ r0      * N_TOT + col] = v0;
            *(float2*)&Y[(r0 + 8) * N_TOT + col] = v1;
        }
    }
#pragma unroll
    for (int ni = 0; ni < 8; ni++) {
#pragma unroll
        for (int j = 0; j < 2; j++) {
            float s = c[0][ni][j] + c[0][ni][j + 2] + c[1][ni][j] + c[1][ni][j + 2];
            float q = c[0][ni][j]     * c[0][ni][j]
                    + c[0][ni][j + 2] * c[0][ni][j + 2]
                    + c[1][ni][j]     * c[1][ni][j]
                    + c[1][ni][j + 2] * c[1][ni][j + 2];
#pragma unroll
            for (int m = 16; m >= 4; m >>= 1) {
                s += __shfl_xor_sync(0xffffffffu, s, m);
                q += __shfl_xor_sync(0xffffffffu, q, m);
            }
            if (lane < 4) {
                int cch = warpCol * 64 + ni * 8 + tg * 2 + j;
                atomicAdd(&ssum[cch], s);
                atomicAdd(&ssq [cch], q);
            }
        }
    }
    __syncthreads();
    if (tid < 128) {
        atomicAdd(&d_sum  [layer_out * 256 + colBase + tid], ssum[tid]);
        atomicAdd(&d_sumsq[layer_out * 256 + colBase + tid], ssq[tid]);
    }
}

// ---------------------------------------------------------------------------
// Final epilogue: out = lrelu( BN_sc(SC) + mean_k lrelu(BN2(y2)) )
// ---------------------------------------------------------------------------
__global__ void final_kernel(float* __restrict__ out) {
    int t = blockIdx.x * blockDim.x + threadIdx.x;
    if (t >= NPTS * 64) return;
    int np = t >> 6, c4 = t & 63;
    float4 s2 = *(const float4*)&d_scale[2 * 256 + c4 * 4];
    float4 h2 = *(const float4*)&d_shift[2 * 256 + c4 * 4];
    float4 s3 = *(const float4*)&d_scale[3 * 256 + c4 * 4];
    float4 h3 = *(const float4*)&d_shift[3 * 256 + c4 * 4];
    const float4* Y4 = (const float4*)d_buf3;
    size_t base = (size_t)np * 16 * 64 + c4;
    float ax = 0, ay = 0, az = 0, aw = 0;
#pragma unroll
    for (int k = 0; k < KNN; k++) {
        float4 v = Y4[base + (size_t)k * 64];
        float x0 = v.x * s2.x + h2.x, x1 = v.y * s2.y + h2.y;
        float x2 = v.z * s2.z + h2.z, x3 = v.w * s2.w + h2.w;
        ax += x0 > 0.f ? x0 : LRELU_ALPHA * x0;
        ay += x1 > 0.f ? x1 : LRELU_ALPHA * x1;
        az += x2 > 0.f ? x2 : LRELU_ALPHA * x2;
        aw += x3 > 0.f ? x3 : LRELU_ALPHA * x3;
    }
    const float inv = 1.0f / (float)KNN;
    float4 s = ((const float4*)d_SC)[np * 64 + c4];
    float r0 = s.x * s3.x + h3.x + ax * inv;
    float r1 = s.y * s3.y + h3.y + ay * inv;
    float r2 = s.z * s3.z + h3.z + az * inv;
    float r3 = s.w * s3.w + h3.w + aw * inv;
    float4 o;
    o.x = r0 > 0.f ? r0 : LRELU_ALPHA * r0;
    o.y = r1 > 0.f ? r1 : LRELU_ALPHA * r1;
    o.z = r2 > 0.f ? r2 : LRELU_ALPHA * r2;
    o.w = r3 > 0.f ? r3 : LRELU_ALPHA * r3;
    ((float4*)out)[t] = o;
}

// ---------------------------------------------------------------------------
// Launch
// ---------------------------------------------------------------------------
extern "C" void kernel_launch(void* const* d_in, const int* in_sizes, int n_in,
                              void* d_out, int out_size) {
    const float* points   = (const float*)d_in[0];
    const float* features = (const float*)d_in[1];
    const float* W0  = (const float*)d_in[2];
    const float* g0  = (const float*)d_in[3];
    const float* b0  = (const float*)d_in[4];
    const float* W1  = (const float*)d_in[5];
    const float* g1  = (const float*)d_in[6];
    const float* b1  = (const float*)d_in[7];
    const float* W2  = (const float*)d_in[8];
    const float* g2  = (const float*)d_in[9];
    const float* b2  = (const float*)d_in[10];
    const float* Wsc = (const float*)d_in[11];
    const float* gsc = (const float*)d_in[12];
    const float* bsc = (const float*)d_in[13];
    float* out = (float*)d_out;

    float *pA, *pB, *pSC, *p2, *p3, *pWA, *psum, *psq;
    cudaGetSymbolAddress((void**)&pA,  d_A);
    cudaGetSymbolAddress((void**)&pB,  d_B);
    cudaGetSymbolAddress((void**)&pSC, d_SC);
    cudaGetSymbolAddress((void**)&p2,  d_buf2);
    cudaGetSymbolAddress((void**)&p3,  d_buf3);
    cudaGetSymbolAddress((void**)&pWA, d_WA);
    cudaGetSymbolAddress((void**)&psum, d_sum);
    cudaGetSymbolAddress((void**)&psq,  d_sumsq);

    constexpr int SMEM_MMA = (2 * 128 * APAD) * 4 + 2 * 128 * 4 + 256; // ~136KB
    cudaFuncSetAttribute(gemm_mma_kernel<128, 0>,
                         cudaFuncAttributeMaxDynamicSharedMemorySize, SMEM_MMA);
    cudaFuncSetAttribute(gemm_mma_kernel<256, 1>,
                         cudaFuncAttributeMaxDynamicSharedMemorySize, SMEM_MMA);

    zero_stats_kernel<<<4, 256>>>();
    knn_kernel<<<128, 256>>>(points);
    prep_wa_kernel<<<32, 256>>>(W0);

    // A = f @ WA ; B = f @ W0[64:] ; SC = f @ Wsc (stats -> layer 3)
    gemm_kernel<false><<<dim3(NPTS / GBM, 1), 256>>>(features, pWA, pA,
                                                     NPTS, 64, 128, nullptr, nullptr);
    gemm_kernel<false><<<dim3(NPTS / GBM, 1), 256>>>(features, W0 + 64 * 128, pB,
                                                     NPTS, 64, 128, nullptr, nullptr);
    gemm_kernel<true><<<dim3(NPTS / GBM, 2), 256>>>(features, Wsc, pSC,
                                                    NPTS, 64, 256,
                                                    psum + 3 * 256, psq + 3 * 256);
    finalize_kernel<<<1, 256>>>(3, gsc, bsc, (float)NPTS, 256);

    // layer 0 stats (virtual y0), finalize BN0
    l0_stats_kernel<<<2048, 256>>>();
    finalize_kernel<<<1, 256>>>(0, g0, b0, (float)ROWS, 128);

    // layer 1: fused gather+BN0+lrelu -> tf32 MMA -> y1 + stats
    gemm_mma_kernel<128, 0><<<dim3(ROWS / 128, 1), 256, SMEM_MMA>>>(nullptr, W1, p2, 0, 1);
    finalize_kernel<<<1, 256>>>(1, g1, b1, (float)ROWS, 128);

    // layer 2: fused BN1+lrelu -> tf32 MMA -> y2 + stats
    gemm_mma_kernel<256, 1><<<dim3(ROWS / 128, 2), 256, SMEM_MMA>>>(p2, W2, p3, 1, 2);
    finalize_kernel<<<1, 256>>>(2, g2, b2, (float)ROWS, 256);

    final_kernel<<<NPTS * 64 / 256, 256>>>(out);
}

// round 4
// speedup vs baseline: 1.9596x; 1.8428x over previous
#include <cuda_runtime.h>
#include <cuda_fp16.h>
#include <math.h>
#include <cstdint>

// ---------------------------------------------------------------------------
// Problem constants
// ---------------------------------------------------------------------------
#define NB   32
#define PP   1024
#define C0   64
#define KNN  16
#define NPTS (NB * PP)       // 32768
#define ROWS (NPTS * KNN)    // 524288
#define LRELU_ALPHA 0.1f
#define BN_EPS 1e-3f

// ---------------------------------------------------------------------------
// Static device scratch
// ---------------------------------------------------------------------------
__device__ float  d_A  [NPTS * 128];     // features @ (W0[:64]-W0[64:])
__device__ float  d_B  [NPTS * 128];     // features @ W0[64:]
__device__ float  d_SC [NPTS * 256];     // features @ Wsc (pre-BN)
__device__ __half d_y1 [ROWS * 128];     // y1 (pre-BN, fp16)
__device__ __half d_y2 [(size_t)ROWS * 256];  // y2 (pre-BN, fp16)
__device__ int    d_idx [ROWS];
__device__ float  d_WA  [64 * 128];
__device__ float  d_sum  [4 * 256];
__device__ float  d_sumsq[4 * 256];
__device__ float  d_scale[4 * 256];
__device__ float  d_shift[4 * 256];

__device__ __forceinline__ void mma_f16(float* d, const uint32_t* a, const uint32_t* b) {
    asm volatile(
        "mma.sync.aligned.m16n8k16.row.col.f32.f16.f16.f32 "
        "{%0,%1,%2,%3}, {%4,%5,%6,%7}, {%8,%9}, {%0,%1,%2,%3};"
        : "+f"(d[0]), "+f"(d[1]), "+f"(d[2]), "+f"(d[3])
        : "r"(a[0]), "r"(a[1]), "r"(a[2]), "r"(a[3]), "r"(b[0]), "r"(b[1]));
}
__device__ __forceinline__ uint32_t pack_h2(float lo, float hi) {
    __half2 h = __floats2half2_rn(lo, hi);
    return *(uint32_t*)&h;
}
__device__ __forceinline__ float lrelu(float x) {
    return x > 0.f ? x : LRELU_ALPHA * x;
}

// ---------------------------------------------------------------------------
// Fused: zero stats + WA = W0[:64]-W0[64:]
// ---------------------------------------------------------------------------
__global__ void setup_kernel(const float* __restrict__ W0) {
    int t = blockIdx.x * blockDim.x + threadIdx.x;
    if (t < 4 * 256) { d_sum[t] = 0.f; d_sumsq[t] = 0.f; }
    if (t < 64 * 128) d_WA[t] = W0[t] - W0[64 * 128 + t];
}

// ---------------------------------------------------------------------------
// KNN: 16 nearest excluding self (order irrelevant; consumed via mean over k)
// ---------------------------------------------------------------------------
__global__ void knn_kernel(const float* __restrict__ pts) {
    __shared__ float sx[PP], sy[PP], sz[PP];
    int n = blockIdx.x >> 2;
    int p = ((blockIdx.x & 3) << 8) + threadIdx.x;
    const float* base = pts + (size_t)n * PP * 3;
    for (int i = threadIdx.x; i < PP; i += blockDim.x) {
        sx[i] = base[i * 3 + 0];
        sy[i] = base[i * 3 + 1];
        sz[i] = base[i * 3 + 2];
    }
    __syncthreads();
    float qx = sx[p], qy = sy[p], qz = sz[p];
    float bd[KNN]; int bi[KNN];
#pragma unroll
    for (int i = 0; i < KNN; i++) { bd[i] = 3.0e38f; bi[i] = 0; }
    for (int q = 0; q < PP; q++) {
        float dx = sx[q] - qx, dy = sy[q] - qy, dz = sz[q] - qz;
        float d = dx * dx + dy * dy + dz * dz;
        if (q == p) continue;
        if (d < bd[KNN - 1]) {
            int j = KNN - 1;
            while (j > 0 && bd[j - 1] > d) { bd[j] = bd[j - 1]; bi[j] = bi[j - 1]; j--; }
            bd[j] = d; bi[j] = q;
        }
    }
    int ob = (n * PP + p) * KNN;
    for (int k = 0; k < KNN; k++) d_idx[ob + k] = bi[k];
}

// ---------------------------------------------------------------------------
// SIMT fp32 GEMM (small feature matmuls, M=32768, K=64). DUAL mode computes
// both A and B (grid.y picks the weight/output pair) in one launch.
// ---------------------------------------------------------------------------
#define GBM 128
#define GBN 128
#define GBK 8
template <bool STATS, bool DUAL>
__global__ void gemm_kernel(const float* __restrict__ X, const float* __restrict__ W_,
                            float* __restrict__ Y_, int M, int Kc, int N,
                            const float* __restrict__ W2_, float* __restrict__ Y2_,
                            float* sumArr, float* sumsqArr) {
    const float* W = W_;
    float* Y = Y_;
    int colBase = blockIdx.y * GBN;
    if (DUAL) {
        if (blockIdx.y == 1) { W = W2_; Y = Y2_; }
        colBase = 0;
    }
    __shared__ float As[GBK][GBM];
    __shared__ float Bs[GBK][GBN];
    int tid = threadIdx.x;
    int rowBase = blockIdx.x * GBM;
    int tx = tid & 15, ty = tid >> 4;
    float acc[8][8];
#pragma unroll
    for (int i = 0; i < 8; i++)
#pragma unroll
        for (int j = 0; j < 8; j++) acc[i][j] = 0.f;
    int a_row = tid >> 1, a_k4 = (tid & 1) * 4;
    int b_k = tid >> 5, b_n = (tid & 31) * 4;
    for (int k0 = 0; k0 < Kc; k0 += GBK) {
        float4 av = *(const float4*)&X[(size_t)(rowBase + a_row) * Kc + k0 + a_k4];
        As[a_k4 + 0][a_row] = av.x; As[a_k4 + 1][a_row] = av.y;
        As[a_k4 + 2][a_row] = av.z; As[a_k4 + 3][a_row] = av.w;
        float4 bv = *(const float4*)&W[(size_t)(k0 + b_k) * N + colBase + b_n];
        *(float4*)&Bs[b_k][b_n] = bv;
        __syncthreads();
#pragma unroll
        for (int kk = 0; kk < GBK; kk++) {
            float4 a0 = *(const float4*)&As[kk][ty * 8];
            float4 a1 = *(const float4*)&As[kk][ty * 8 + 4];
            float4 b0 = *(const float4*)&Bs[kk][tx * 8];
            float4 b1 = *(const float4*)&Bs[kk][tx * 8 + 4];
            float a[8] = {a0.x, a0.y, a0.z, a0.w, a1.x, a1.y, a1.z, a1.w};
            float b[8] = {b0.x, b0.y, b0.z, b0.w, b1.x, b1.y, b1.z, b1.w};
#pragma unroll
            for (int i = 0; i < 8; i++)
#pragma unroll
                for (int j = 0; j < 8; j++) acc[i][j] += a[i] * b[j];
        }
        __syncthreads();
    }
#pragma unroll
    for (int i = 0; i < 8; i++) {
        int row = rowBase + ty * 8 + i;
        float4 c0 = {acc[i][0], acc[i][1], acc[i][2], acc[i][3]};
        float4 c1 = {acc[i][4], acc[i][5], acc[i][6], acc[i][7]};
        *(float4*)&Y[(size_t)row * N + colBase + tx * 8]     = c0;
        *(float4*)&Y[(size_t)row * N + colBase + tx * 8 + 4] = c1;
    }
    if constexpr (STATS) {
        __shared__ float ssum[GBN], ssq[GBN];
        if (tid < GBN) { ssum[tid] = 0.f; ssq[tid] = 0.f; }
        __syncthreads();
#pragma unroll
        for (int j = 0; j < 8; j++) {
            float s = 0.f, q = 0.f;
#pragma unroll
            for (int i = 0; i < 8; i++) { s += acc[i][j]; q += acc[i][j] * acc[i][j]; }
            atomicAdd(&ssum[tx * 8 + j], s);
            atomicAdd(&ssq [tx * 8 + j], q);
        }
        __syncthreads();
        if (tid < GBN) {
            atomicAdd(&sumArr  [colBase + tid], ssum[tid]);
            atomicAdd(&sumsqArr[colBase + tid], ssq[tid]);
        }
    }
}

// ---------------------------------------------------------------------------
// Layer-0 BN stats without materializing y0: y0 = A[np] + B[idx]
// ---------------------------------------------------------------------------
__global__ void l0_stats_kernel() {
    const float4* A4 = (const float4*)d_A;
    const float4* B4 = (const float4*)d_B;
    __shared__ float ssum[128], ssq[128];
    if (threadIdx.x < 128) { ssum[threadIdx.x] = 0.f; ssq[threadIdx.x] = 0.f; }
    __syncthreads();
    int start  = blockIdx.x * blockDim.x + threadIdx.x;
    int stride = gridDim.x * blockDim.x;
    int c4 = start & 31;
    const int total = ROWS * 32;
    float s0 = 0, s1 = 0, s2 = 0, s3 = 0;
    float q0 = 0, q1 = 0, q2 = 0, q3 = 0;
    for (int e = start; e < total; e += stride) {
        int r = e >> 5, cc = e & 31;
        int np = r >> 4, n = np >> 10;
        int id = d_idx[r];
        float4 a = A4[np * 32 + cc];
        float4 b = B4[(n * 1024 + id) * 32 + cc];
        float yx = a.x + b.x, yy = a.y + b.y, yz = a.z + b.z, yw = a.w + b.w;
        s0 += yx; q0 += yx * yx; s1 += yy; q1 += yy * yy;
        s2 += yz; q2 += yz * yz; s3 += yw; q3 += yw * yw;
    }
    atomicAdd(&ssum[c4 * 4 + 0], s0); atomicAdd(&ssq[c4 * 4 + 0], q0);
    atomicAdd(&ssum[c4 * 4 + 1], s1); atomicAdd(&ssq[c4 * 4 + 1], q1);
    atomicAdd(&ssum[c4 * 4 + 2], s2); atomicAdd(&ssq[c4 * 4 + 2], q2);
    atomicAdd(&ssum[c4 * 4 + 3], s3); atomicAdd(&ssq[c4 * 4 + 3], q3);
    __syncthreads();
    if (threadIdx.x < 128) {
        atomicAdd(&d_sum  [threadIdx.x], ssum[threadIdx.x]);
        atomicAdd(&d_sumsq[threadIdx.x], ssq[threadIdx.x]);
    }
}

__global__ void finalize_kernel(int layer, const float* __restrict__ g,
                                const float* __restrict__ b, float cnt, int nch) {
    int c = threadIdx.x;
    if (c < nch) {
        float mean = d_sum[layer * 256 + c] / cnt;
        float var  = d_sumsq[layer * 256 + c] / cnt - mean * mean;
        float sc = g[c] * rsqrtf(var + BN_EPS);
        d_scale[layer * 256 + c] = sc;
        d_shift[layer * 256 + c] = b[c] - mean * sc;
    }
}

// ---------------------------------------------------------------------------
// fp16 mma.sync GEMM: BM=128, BN=128, K=128 in one shot, m16n8k16.
// 256 thr = 8 warps (4 row x 2 col), warp tile 32x64, 8 K-steps.
// MODE 0: A-tile = lrelu(BN0(gather A+B))  -> layer-1 GEMM, out fp16
// MODE 1: A-tile = lrelu(BN1(y1 fp16))     -> layer-2 GEMM, out fp16
// Epilogue: raw y (fp16) + per-channel sum/sumsq (fp32 exact accums).
// smem rows: 64 words (packed half2) + 4 pad = 68 -> conflict-free LDS.
// ---------------------------------------------------------------------------
#define KW 68
template <int N_TOT, int MODE>
__global__ void __launch_bounds__(256, 2) gemm_mma_kernel(
    const __half* __restrict__ Xin, const float* __restrict__ W,
    __half* __restrict__ Y, int layer_in, int layer_out) {
    extern __shared__ char smem_raw[];
    uint32_t* As = (uint32_t*)smem_raw;                    // [128][KW] half2 words
    uint32_t* Bs = As + 128 * KW;                          // [128][KW]
    float*  ssum = (float*)(Bs + 128 * KW);                // [128]
    float*  ssq  = ssum + 128;

    const int tid = threadIdx.x;
    const int wid = tid >> 5;
    const int lane = tid & 31;
    const int gid = lane >> 2;
    const int tg  = lane & 3;
    const int warpRow = wid & 3;
    const int warpCol = wid >> 2;
    const int tileBase = blockIdx.x * 128;
    const int colBase  = blockIdx.y * 128;

    if (tid < 128) { ssum[tid] = 0.f; ssq[tid] = 0.f; }

    // ---- B tile: Bs[n][kw] = half2(W[2kw][col], W[2kw+1][col]) -------------
    for (int e = tid; e < 128 * 64; e += 256) {
        int n = e & 127, kw = e >> 7;
        float w0 = W[(size_t)(2 * kw)     * N_TOT + colBase + n];
        float w1 = W[(size_t)(2 * kw + 1) * N_TOT + colBase + n];
        Bs[n * KW + kw] = pack_h2(w0, w1);
    }

    // ---- A tile (fused elementwise producer), 8 channels per iteration -----
    const float4* sc4 = (const float4*)&d_scale[layer_in * 256];
    const float4* sh4 = (const float4*)&d_shift[layer_in * 256];
    for (int e = tid; e < 128 * 16; e += 256) {
        int r = e >> 4, cw = e & 15;           // cw: chunk of 8 channels
        int R = tileBase + r;
        float x[8];
        if (MODE == 0) {
            int np = R >> 4, n = np >> 10;
            int id = d_idx[R];
            float4 a0 = ((const float4*)d_A)[np * 32 + cw * 2];
            float4 a1 = ((const float4*)d_A)[np * 32 + cw * 2 + 1];
            float4 b0 = ((const float4*)d_B)[(n * 1024 + id) * 32 + cw * 2];
            float4 b1 = ((const float4*)d_B)[(n * 1024 + id) * 32 + cw * 2 + 1];
            x[0] = a0.x + b0.x; x[1] = a0.y + b0.y; x[2] = a0.z + b0.z; x[3] = a0.w + b0.w;
            x[4] = a1.x + b1.x; x[5] = a1.y + b1.y; x[6] = a1.z + b1.z; x[7] = a1.w + b1.w;
        } else {
            uint4 h = ((const uint4*)&Xin[(size_t)R * 128])[cw];
            uint32_t hw[4] = {h.x, h.y, h.z, h.w};
#pragma unroll
            for (int j = 0; j < 4; j++) {
                float2 f = __half22float2(*(__half2*)&hw[j]);
                x[j * 2] = f.x; x[j * 2 + 1] = f.y;
            }
        }
        float4 sca = sc4[cw * 2], scb = sc4[cw * 2 + 1];
        float4 sha = sh4[cw * 2], shb = sh4[cw * 2 + 1];
        float y[8];
        y[0] = lrelu(x[0] * sca.x + sha.x); y[1] = lrelu(x[1] * sca.y + sha.y);
        y[2] = lrelu(x[2] * sca.z + sha.z); y[3] = lrelu(x[3] * sca.w + sha.w);
        y[4] = lrelu(x[4] * scb.x + shb.x); y[5] = lrelu(x[5] * scb.y + shb.y);
        y[6] = lrelu(x[6] * scb.z + shb.z); y[7] = lrelu(x[7] * scb.w + shb.w);
        uint32_t* dst = &As[r * KW + cw * 4];
        dst[0] = pack_h2(y[0], y[1]); dst[1] = pack_h2(y[2], y[3]);
        dst[2] = pack_h2(y[4], y[5]); dst[3] = pack_h2(y[6], y[7]);
    }
    __syncthreads();

    // ---- MMA main: warp tile 32x64, 8 K-steps of k16 -----------------------
    float c[2][8][4];
#pragma unroll
    for (int mi = 0; mi < 2; mi++)
#pragma unroll
        for (int ni = 0; ni < 8; ni++)
#pragma unroll
            for (int j = 0; j < 4; j++) c[mi][ni][j] = 0.f;

#pragma unroll
    for (int k0 = 0; k0 < 8; k0++) {
        uint32_t af[2][4], bf[8][2];
#pragma unroll
        for (int mi = 0; mi < 2; mi++) {
            int mb = warpRow * 32 + mi * 16;
            af[mi][0] = As[(mb + gid    ) * KW + k0 * 8 + tg];
            af[mi][1] = As[(mb + gid + 8) * KW + k0 * 8 + tg];
            af[mi][2] = As[(mb + gid    ) * KW + k0 * 8 + tg + 4];
            af[mi][3] = As[(mb + gid + 8) * KW + k0 * 8 + tg + 4];
        }
#pragma unroll
        for (int ni = 0; ni < 8; ni++) {
            int nb = warpCol * 64 + ni * 8 + gid;
            bf[ni][0] = Bs[nb * KW + k0 * 8 + tg];
            bf[ni][1] = Bs[nb * KW + k0 * 8 + tg + 4];
        }
#pragma unroll
        for (int mi = 0; mi < 2; mi++)
#pragma unroll
            for (int ni = 0; ni < 8; ni++)
                mma_f16(c[mi][ni], af[mi], bf[ni]);
    }

    // ---- Epilogue: store fp16 y, accumulate stats --------------------------
#pragma unroll
    for (int mi = 0; mi < 2; mi++) {
        size_t r0 = (size_t)tileBase + warpRow * 32 + mi * 16 + gid;
#pragma unroll
        for (int ni = 0; ni < 8; ni++) {
            int col = colBase + warpCol * 64 + ni * 8 + tg * 2;
            __half2 v0 = __floats2half2_rn(c[mi][ni][0], c[mi][ni][1]);
            __half2 v1 = __floats2half2_rn(c[mi][ni][2], c[mi][ni][3]);
            *(__half2*)&Y[ r0      * N_TOT + col] = v0;
            *(__half2*)&Y[(r0 + 8) * N_TOT + col] = v1;
        }
    }
#pragma unroll
    for (int ni = 0; ni < 8; ni++) {
#pragma unroll
        for (int j = 0; j < 2; j++) {
            float s = c[0][ni][j] + c[0][ni][j + 2] + c[1][ni][j] + c[1][ni][j + 2];
            float q = c[0][ni][j]     * c[0][ni][j]
                    + c[0][ni][j + 2] * c[0][ni][j + 2]
                    + c[1][ni][j]     * c[1][ni][j]
                    + c[1][ni][j + 2] * c[1][ni][j + 2];
#pragma unroll
            for (int m = 16; m >= 4; m >>= 1) {
                s += __shfl_xor_sync(0xffffffffu, s, m);
                q += __shfl_xor_sync(0xffffffffu, q, m);
            }
            if (lane < 4) {
                int cch = warpCol * 64 + ni * 8 + tg * 2 + j;
                atomicAdd(&ssum[cch], s);
                atomicAdd(&ssq [cch], q);
            }
        }
    }
    __syncthreads();
    if (tid < 128) {
        atomicAdd(&d_sum  [layer_out * 256 + colBase + tid], ssum[tid]);
        atomicAdd(&d_sumsq[layer_out * 256 + colBase + tid], ssq[tid]);
    }
}

// ---------------------------------------------------------------------------
// Final epilogue: out = lrelu( BN_sc(SC) + mean_k lrelu(BN2(y2)) )
// ---------------------------------------------------------------------------
__global__ void final_kernel(float* __restrict__ out) {
    int t = blockIdx.x * blockDim.x + threadIdx.x;
    if (t >= NPTS * 64) return;
    int np = t >> 6, c4 = t & 63;
    float4 s2 = *(const float4*)&d_scale[2 * 256 + c4 * 4];
    float4 h2 = *(const float4*)&d_shift[2 * 256 + c4 * 4];
    float4 s3 = *(const float4*)&d_scale[3 * 256 + c4 * 4];
    float4 h3 = *(const float4*)&d_shift[3 * 256 + c4 * 4];
    const uint2* Y2 = (const uint2*)d_y2;   // 4 halves per uint2
    size_t base = (size_t)np * 16 * 64 + c4;
    float ax = 0, ay = 0, az = 0, aw = 0;
#pragma unroll
    for (int k = 0; k < KNN; k++) {
        uint2 hv = Y2[base + (size_t)k * 64];
        float2 f01 = __half22float2(*(__half2*)&hv.x);
        float2 f23 = __half22float2(*(__half2*)&hv.y);
        ax += lrelu(f01.x * s2.x + h2.x);
        ay += lrelu(f01.y * s2.y + h2.y);
        az += lrelu(f23.x * s2.z + h2.z);
        aw += lrelu(f23.y * s2.w + h2.w);
    }
    const float inv = 1.0f / (float)KNN;
    float4 s = ((const float4*)d_SC)[np * 64 + c4];
    float4 o;
    o.x = lrelu(s.x * s3.x + h3.x + ax * inv);
    o.y = lrelu(s.y * s3.y + h3.y + ay * inv);
    o.z = lrelu(s.z * s3.z + h3.z + az * inv);
    o.w = lrelu(s.w * s3.w + h3.w + aw * inv);
    ((float4*)out)[t] = o;
}

// ---------------------------------------------------------------------------
// Launch. Order chosen so the 6th launch (ncu -s 5 -c 1) is gemm_mma<128,0>.
// ---------------------------------------------------------------------------
extern "C" void kernel_launch(void* const* d_in, const int* in_sizes, int n_in,
                              void* d_out, int out_size) {
    const float* points   = (const float*)d_in[0];
    const float* features = (const float*)d_in[1];
    const float* W0  = (const float*)d_in[2];
    const float* g0  = (const float*)d_in[3];
    const float* b0  = (const float*)d_in[4];
    const float* W1  = (const float*)d_in[5];
    const float* g1  = (const float*)d_in[6];
    const float* b1  = (const float*)d_in[7];
    const float* W2  = (const float*)d_in[8];
    const float* g2  = (const float*)d_in[9];
    const float* b2  = (const float*)d_in[10];
    const float* Wsc = (const float*)d_in[11];
    const float* gsc = (const float*)d_in[12];
    const float* bsc = (const float*)d_in[13];
    float* out = (float*)d_out;

    float *pA, *pB, *pSC, *pWA, *psum, *psq;
    __half *p1, *p2;
    cudaGetSymbolAddress((void**)&pA,  d_A);
    cudaGetSymbolAddress((void**)&pB,  d_B);
    cudaGetSymbolAddress((void**)&pSC, d_SC);
    cudaGetSymbolAddress((void**)&p1,  d_y1);
    cudaGetSymbolAddress((void**)&p2,  d_y2);
    cudaGetSymbolAddress((void**)&pWA, d_WA);
    cudaGetSymbolAddress((void**)&psum, d_sum);
    cudaGetSymbolAddress((void**)&psq,  d_sumsq);

    constexpr int SMEM_MMA = (2 * 128 * KW) * 4 + 2 * 128 * 4 + 256;   // ~71KB
    cudaFuncSetAttribute(gemm_mma_kernel<128, 0>,
                         cudaFuncAttributeMaxDynamicSharedMemorySize, SMEM_MMA);
    cudaFuncSetAttribute(gemm_mma_kernel<256, 1>,
                         cudaFuncAttributeMaxDynamicSharedMemorySize, SMEM_MMA);

    // 1: setup (zero stats + WA)
    setup_kernel<<<32, 256>>>(W0);
    // 2: knn
    knn_kernel<<<128, 256>>>(points);
    // 3: A = f@WA and B = f@W0[64:] in one dual launch
    gemm_kernel<false, true><<<dim3(NPTS / GBM, 2), 256>>>(
        features, pWA, pA, NPTS, 64, 128, W0 + 64 * 128, pB, nullptr, nullptr);
    // 4: layer-0 stats (virtual y0)
    l0_stats_kernel<<<2048, 256>>>();
    // 5: finalize BN0
    finalize_kernel<<<1, 256>>>(0, g0, b0, (float)ROWS, 128);
    // 6: layer 1 MMA (PROFILED by ncu)
    gemm_mma_kernel<128, 0><<<dim3(ROWS / 128, 1), 256, SMEM_MMA>>>(nullptr, W1, p1, 0, 1);
    // 7: finalize BN1
    finalize_kernel<<<1, 256>>>(1, g1, b1, (float)ROWS, 128);
    // 8: shortcut SC = f @ Wsc (+ stats -> layer 3)
    gemm_kernel<true, false><<<dim3(NPTS / GBM, 2), 256>>>(
        features, Wsc, pSC, NPTS, 64, 256, nullptr, nullptr,
        psum + 3 * 256, psq + 3 * 256);
    // 9: finalize BN_sc
    finalize_kernel<<<1, 256>>>(3, gsc, bsc, (float)NPTS, 256);
    // 10: layer 2 MMA
    gemm_mma_kernel<256, 1><<<dim3(ROWS / 128, 2), 256, SMEM_MMA>>>(p1, W2, p2, 1, 2);
    // 11: finalize BN2
    finalize_kernel<<<1, 256>>>(2, g2, b2, (float)ROWS, 256);
    // 12: final epilogue
    final_kernel<<<NPTS * 64 / 256, 256>>>(out);
}